// round 1
// baseline (speedup 1.0000x reference)
#include <cuda_runtime.h>
#include <cuda_bf16.h>

// Problem: SurvivalGeometryRegularizer — pairwise ranking hinge loss.
//   mask[i][j] = (time[i] < time[j]) && (event[i] == 1)
//   hinge[i][j] = relu(1 - (risk[j] - risk[i])) = max(0, (1 + risk[i]) - risk[j])
//   out = sum(mask*hinge) / sum(mask)   (0 if count==0)
// NOTE: input z (8192x128) is UNUSED by the reference. Only risk/time/event matter.
//
// Inputs (metadata order): d_in[0]=z (f32, unused), d_in[1]=risk (f32 [B]),
//                          d_in[2]=time (f32 [B]), d_in[3]=event (i32 [B]).
// Output: single f32 scalar.

#define BB 8192
#define TPB 256          // threads per block (one i per thread)
#define JT 512           // j-tile size held in smem
#define IB (BB / TPB)    // 32 i-blocks
#define JB (BB / JT)     // 16 j-blocks
#define NPART (IB * JB)  // 512 partial slots

// Fixed-slot partial results (deterministic: no atomics anywhere).
__device__ double             g_psum[NPART];
__device__ unsigned long long g_pcnt[NPART];

__global__ __launch_bounds__(TPB) void pair_hinge_kernel(
    const float* __restrict__ risk,
    const float* __restrict__ time_,
    const int*   __restrict__ event)
{
    __shared__ float2 sj[JT];           // (time[j], risk[j])
    __shared__ float  red_s[TPB / 32];
    __shared__ int    red_c[TPB / 32];

    const int tid = threadIdx.x;
    const int i   = blockIdx.x * TPB + tid;
    const int j0  = blockIdx.y * JT;

    // Stage the j-tile into shared memory (coalesced global reads, L2-hot).
    #pragma unroll
    for (int k = tid; k < JT; k += TPB) {
        sj[k] = make_float2(time_[j0 + k], risk[j0 + k]);
    }
    __syncthreads();

    // Per-thread row data. event==0 rows: force t_i = +INF so the strict
    // compare (t_i < t_j) is always false -> zero contribution, no divergence.
    const float INF = __int_as_float(0x7f800000);
    const float ti  = event[i] ? time_[i] : INF;
    const float ai  = 1.0f + risk[i];

    float s = 0.0f;
    int   c = 0;

    #pragma unroll 16
    for (int k = 0; k < JT; k++) {
        const float2 v = sj[k];               // broadcast LDS.64 (same addr across warp)
        const bool   m = ti < v.x;            // FSETP
        const float  h = fmaxf(ai - v.y, 0.0f); // FADD + FMNMX
        if (m) {                               // predicated FADD / IADD
            s += h;
            c += 1;
        }
    }

    // Deterministic intra-block reduction: warp shuffle tree, then warp 0.
    #pragma unroll
    for (int off = 16; off > 0; off >>= 1) {
        s += __shfl_down_sync(0xffffffffu, s, off);
        c += __shfl_down_sync(0xffffffffu, c, off);
    }
    const int lane = tid & 31;
    const int wid  = tid >> 5;
    if (lane == 0) { red_s[wid] = s; red_c[wid] = c; }
    __syncthreads();

    if (wid == 0) {
        float sv = (lane < TPB / 32) ? red_s[lane] : 0.0f;
        int   cv = (lane < TPB / 32) ? red_c[lane] : 0;
        #pragma unroll
        for (int off = 4; off > 0; off >>= 1) {
            sv += __shfl_down_sync(0xffffffffu, sv, off);
            cv += __shfl_down_sync(0xffffffffu, cv, off);
        }
        if (lane == 0) {
            const int slot = blockIdx.y * IB + blockIdx.x;
            g_psum[slot] = (double)sv;
            g_pcnt[slot] = (unsigned long long)cv;
        }
    }
}

// Single-block deterministic final reduction over the NPART fixed slots.
__global__ __launch_bounds__(NPART) void finalize_kernel(float* __restrict__ out)
{
    __shared__ double             rs[NPART];
    __shared__ unsigned long long rc[NPART];

    const int tid = threadIdx.x;
    rs[tid] = g_psum[tid];
    rc[tid] = g_pcnt[tid];
    __syncthreads();

    #pragma unroll
    for (int off = NPART / 2; off > 0; off >>= 1) {
        if (tid < off) {
            rs[tid] += rs[tid + off];
            rc[tid] += rc[tid + off];
        }
        __syncthreads();
    }

    if (tid == 0) {
        const double total = rs[0];
        const unsigned long long cnt = rc[0];
        out[0] = (cnt == 0ull) ? 0.0f : (float)(total / (double)cnt);
    }
}

extern "C" void kernel_launch(void* const* d_in, const int* in_sizes, int n_in,
                              void* d_out, int out_size)
{
    // d_in[0] = z (unused)
    const float* risk  = (const float*)d_in[1];
    const float* time_ = (const float*)d_in[2];
    const int*   event = (const int*)d_in[3];
    float* out = (float*)d_out;

    dim3 grid(IB, JB);
    pair_hinge_kernel<<<grid, TPB>>>(risk, time_, event);
    finalize_kernel<<<1, NPART>>>(out);
}